// round 9
// baseline (speedup 1.0000x reference)
#include <cuda_runtime.h>
#include <cuda_bf16.h>
#include <cstdint>

// BoxFilter r=8 (k=17), separable, zero padding, fused (R6 structure).
// Phase A: interior-x CTAs fill the 80x80 tile with 80 cp.async.bulk row
// copies (320 B each, mbarrier complete_tx) -- 20x fewer issue ops than the
// per-vec4 cp.async path, which is kept only for x-edge CTAs (zfill).
// Then two 32-col halves: horizontal running sums -> s_h (STS.128),
// vertical running sums from registers -> coalesced STG.
// Smem 38.4 KB -> 5 CTAs/SM, regs capped at 40.
// Input x: [8, 32, 512, 512] f32 (256 images of 512x512), same-shape output.

#define RAD 8
#define KW  (2 * RAD + 1)          // 17
#define TILE_W 64
#define TILE_H 64
#define IN_W  (TILE_W + 2 * RAD)   // 80
#define IN_H  (TILE_H + 2 * RAD)   // 80
#define IN_PITCH 84                // 21x16B rows, odd -> LDS.128 conflict-free
#define HALF_W 32
#define HS_PITCH 36                // 9x16B rows, odd -> conflict-free
#define NTHREADS 256
#define ROW_BYTES (IN_W * 4)       // 320, multiple of 16

__global__ __launch_bounds__(NTHREADS, 6)
void box_filter_fused(const float* __restrict__ in, float* __restrict__ out,
                      int H, int W) {
    __shared__ float s_in[IN_H * IN_PITCH];   // 80*84*4 = 26,880 B
    __shared__ float s_h [IN_H * HS_PITCH];   // 80*36*4 = 11,520 B
    __shared__ __align__(8) unsigned long long mbar;

    const int bx  = blockIdx.x;
    const int img = blockIdx.z;
    const int x0  = bx * TILE_W;
    const int y0  = blockIdx.y * TILE_H;
    const int tid = threadIdx.x;

    const float* __restrict__ src = in + (size_t)img * H * W;
    float* __restrict__ dst = out + (size_t)img * H * W;

    const bool interior_x = (bx > 0) && (bx < 7);

    if (interior_x) {
        // ---- Phase A (bulk): 80 row copies of 320 B, zero y-OOB rows ----
        const int r_lo = (y0 - RAD < 0) ? (RAD - y0) : 0;                // first valid slot
        const int r_hi = (y0 - RAD + IN_H > H) ? (H - y0 + RAD) : IN_H;  // end of valid slots

        // zero OOB rows (only y-edge CTAs have any)
        const int nz = r_lo + (IN_H - r_hi);
        if (nz > 0) {
            const float4 z = make_float4(0.f, 0.f, 0.f, 0.f);
            for (int i = tid; i < nz * 21; i += NTHREADS) {
                int k = i / 21, q = i - k * 21;
                int row = (k < r_lo) ? k : (r_hi + k - r_lo);
                *reinterpret_cast<float4*>(&s_in[row * IN_PITCH + 4 * q]) = z;
            }
        }
        unsigned mb = (unsigned)__cvta_generic_to_shared(&mbar);
        if (tid == 0)
            asm volatile("mbarrier.init.shared.b64 [%0], 1;" :: "r"(mb) : "memory");
        __syncthreads();   // mbar init + zero rows visible

        if (tid == 0) {
            unsigned bytes = (unsigned)(r_hi - r_lo) * ROW_BYTES;
            asm volatile("mbarrier.arrive.expect_tx.shared.b64 _, [%0], %1;"
                         :: "r"(mb), "r"(bytes) : "memory");
        }
        if (tid >= r_lo && tid < r_hi) {
            const float* gptr = src + (size_t)(y0 - RAD + tid) * W + (x0 - RAD);
            unsigned saddr = (unsigned)__cvta_generic_to_shared(&s_in[tid * IN_PITCH]);
            asm volatile(
                "cp.async.bulk.shared::cta.global.mbarrier::complete_tx::bytes "
                "[%0], [%1], %2, [%3];"
                :: "r"(saddr), "l"(gptr), "n"(ROW_BYTES), "r"(mb) : "memory");
        }
        // wait (parity 0), all threads
        {
            unsigned done;
            asm volatile(
                "{\n\t.reg .pred p;\n\t"
                "mbarrier.try_wait.parity.shared.b64 p, [%1], 0;\n\t"
                "selp.b32 %0, 1, 0, p;\n\t}"
                : "=r"(done) : "r"(mb) : "memory");
            while (!done) {
                asm volatile(
                    "{\n\t.reg .pred p;\n\t"
                    "mbarrier.try_wait.parity.shared.b64 p, [%1], 0;\n\t"
                    "selp.b32 %0, 1, 0, p;\n\t}"
                    : "=r"(done) : "r"(mb) : "memory");
            }
        }
        __syncthreads();
    } else {
        // ---- Phase A (edge-x): per-vec4 cp.async with zfill ----
        int r = tid / 20;
        int q = tid - r * 20;
        #pragma unroll
        for (int it = 0; it < 7; it++) {
            const int idx = tid + it * NTHREADS;
            if (idx < IN_H * 20) {
                const int gy = y0 - RAD + r;
                const int gx = x0 - RAD + 4 * q;
                const bool ok = ((unsigned)gy < (unsigned)H) &&
                                ((unsigned)gx <= (unsigned)(W - 4));
                const float* gptr = src + (ok ? ((size_t)gy * W + gx) : 0);
                unsigned saddr = (unsigned)__cvta_generic_to_shared(&s_in[r * IN_PITCH + 4 * q]);
                const int sz = ok ? 16 : 0;  // src-size 0 -> zero fill
                asm volatile("cp.async.cg.shared.global [%0], [%1], 16, %2;\n"
                             :: "r"(saddr), "l"(gptr), "r"(sz));
            }
            r += 12; q += 16;
            if (q >= 20) { q -= 20; r += 1; }
        }
        asm volatile("cp.async.commit_group;\n" ::: "memory");
        asm volatile("cp.async.wait_group 0;\n" ::: "memory");
        __syncthreads();
    }

    const float scale = 1.0f / ((float)KW * (float)KW);

    #pragma unroll
    for (int half = 0; half < 2; half++) {
        const int c_base = half * HALF_W;   // tile-local output col base: 0 or 32

        // ---- Phase B: horizontal running sums (160 tasks) ----
        if (tid < IN_H * 2) {
            const int row = tid % IN_H;
            const int stp = tid / IN_H;          // 0..1
            const int ci  = c_base + stp * 16;   // input col start in s_in

            const float* p = &s_in[row * IN_PITCH + ci];
            float v[32];
            #pragma unroll
            for (int j = 0; j < 8; j++) {
                float4 q4 = *reinterpret_cast<const float4*>(p + 4 * j);
                v[4*j + 0] = q4.x; v[4*j + 1] = q4.y;
                v[4*j + 2] = q4.z; v[4*j + 3] = q4.w;
            }

            float h[16];
            float sum = 0.0f;
            #pragma unroll
            for (int j = 0; j < KW; j++) sum += v[j];
            h[0] = sum;
            #pragma unroll
            for (int c = 1; c < 16; c++) {
                sum += v[c + KW - 1] - v[c - 1];
                h[c] = sum;
            }

            float4* hp = reinterpret_cast<float4*>(&s_h[row * HS_PITCH + stp * 16]);
            #pragma unroll
            for (int j = 0; j < 4; j++)
                hp[j] = make_float4(h[4*j], h[4*j+1], h[4*j+2], h[4*j+3]);
        }
        __syncthreads();

        // ---- Phase C: vertical running sums from registers + store (128 tasks) ----
        if (tid < HALF_W * 4) {
            const int col = tid & (HALF_W - 1);
            const int r0  = (tid >> 5) << 4;     // 0,16,32,48

            float v[32];
            #pragma unroll
            for (int j = 0; j < 32; j++)
                v[j] = s_h[(r0 + j) * HS_PITCH + col];

            const int gx = x0 + c_base + col;
            float* p = dst + (size_t)(y0 + r0) * W + gx;

            float sum = 0.0f;
            #pragma unroll
            for (int j = 0; j < KW; j++) sum += v[j];
            *p = sum * scale;

            #pragma unroll
            for (int i = 1; i < 16; i++) {
                sum += v[i + KW - 1] - v[i - 1];
                p += W;
                *p = sum * scale;
            }
        }
        if (half == 0) __syncthreads();
    }
}

extern "C" void kernel_launch(void* const* d_in, const int* in_sizes, int n_in,
                              void* d_out, int out_size) {
    const float* x = (const float*)d_in[0];
    float* out = (float*)d_out;

    const int N = 8, C = 32, H = 512, W = 512;
    (void)in_sizes; (void)n_in; (void)out_size;

    dim3 grid(W / TILE_W, H / TILE_H, N * C);  // 8 x 8 x 256 = 16384 blocks
    box_filter_fused<<<grid, NTHREADS>>>(x, out, H, W);
}

// round 10
// speedup vs baseline: 1.0917x; 1.0917x over previous
#include <cuda_runtime.h>
#include <cuda_bf16.h>

// BoxFilter r=8 (k=17), separable, zero padding, fused (R6 structure).
// Phase A: cp.async.cg (zfill) 80x80 tile load.
// Two 32-col halves: Phase B horizontal running sums (160 tasks) -> s_h,
// Phase C vertical running sums now 256 tasks x 8-row segments (ALL threads
// active; was 128 tasks x 16 rows) -> coalesced STG.
// Smem 38.4 KB -> 5 CTAs/SM, regs capped at 40.
// Input x: [8, 32, 512, 512] f32 (256 images of 512x512), same-shape output.

#define RAD 8
#define KW  (2 * RAD + 1)          // 17
#define TILE_W 64
#define TILE_H 64
#define IN_W  (TILE_W + 2 * RAD)   // 80
#define IN_H  (TILE_H + 2 * RAD)   // 80
#define IN_PITCH 84                // 21x16B rows, odd -> LDS.128 conflict-free
#define HALF_W 32
#define HS_PITCH 36                // 9x16B rows, odd -> conflict-free
#define NTHREADS 256
#define CSEG 8                     // Phase-C rows per task

__global__ __launch_bounds__(NTHREADS, 6)
void box_filter_fused(const float* __restrict__ in, float* __restrict__ out,
                      int H, int W) {
    __shared__ float s_in[IN_H * IN_PITCH];   // 80*84*4 = 26,880 B
    __shared__ float s_h [IN_H * HS_PITCH];   // 80*36*4 = 11,520 B (38.4 KB total)

    const int img = blockIdx.z;
    const int x0  = blockIdx.x * TILE_W;
    const int y0  = blockIdx.y * TILE_H;
    const int tid = threadIdx.x;

    const float* __restrict__ src = in + (size_t)img * H * W;
    float* __restrict__ dst = out + (size_t)img * H * W;

    // ---- Phase A: cp.async tile load (80 rows x 20 float4), zero-filled OOB ----
    {
        int r = tid / 20;
        int q = tid - r * 20;
        #pragma unroll
        for (int it = 0; it < 7; it++) {
            const int idx = tid + it * NTHREADS;
            if (idx < IN_H * 20) {
                const int gy = y0 - RAD + r;
                const int gx = x0 - RAD + 4 * q;
                const bool ok = ((unsigned)gy < (unsigned)H) &&
                                ((unsigned)gx <= (unsigned)(W - 4));
                const float* gptr = src + (ok ? ((size_t)gy * W + gx) : 0);
                unsigned saddr = (unsigned)__cvta_generic_to_shared(&s_in[r * IN_PITCH + 4 * q]);
                const int sz = ok ? 16 : 0;  // src-size 0 -> zero fill
                asm volatile("cp.async.cg.shared.global [%0], [%1], 16, %2;\n"
                             :: "r"(saddr), "l"(gptr), "r"(sz));
            }
            r += 12; q += 16;
            if (q >= 20) { q -= 20; r += 1; }
        }
    }
    asm volatile("cp.async.commit_group;\n" ::: "memory");
    asm volatile("cp.async.wait_group 0;\n" ::: "memory");
    __syncthreads();

    const float scale = 1.0f / ((float)KW * (float)KW);

    #pragma unroll
    for (int half = 0; half < 2; half++) {
        const int c_base = half * HALF_W;   // tile-local output col base: 0 or 32

        // ---- Phase B: horizontal running sums (160 tasks) ----
        if (tid < IN_H * 2) {
            const int row = (tid < IN_H) ? tid : tid - IN_H;
            const int stp = (tid < IN_H) ? 0 : 1;
            const int ci  = c_base + stp * 16;   // input col start in s_in

            const float* p = &s_in[row * IN_PITCH + ci];
            float v[32];
            #pragma unroll
            for (int j = 0; j < 8; j++) {
                float4 q4 = *reinterpret_cast<const float4*>(p + 4 * j);
                v[4*j + 0] = q4.x; v[4*j + 1] = q4.y;
                v[4*j + 2] = q4.z; v[4*j + 3] = q4.w;
            }

            float h[16];
            float sum = 0.0f;
            #pragma unroll
            for (int j = 0; j < KW; j++) sum += v[j];
            h[0] = sum;
            #pragma unroll
            for (int c = 1; c < 16; c++) {
                sum += v[c + KW - 1] - v[c - 1];
                h[c] = sum;
            }

            float4* hp = reinterpret_cast<float4*>(&s_h[row * HS_PITCH + stp * 16]);
            #pragma unroll
            for (int j = 0; j < 4; j++)
                hp[j] = make_float4(h[4*j], h[4*j+1], h[4*j+2], h[4*j+3]);
        }
        __syncthreads();

        // ---- Phase C: vertical running sums, 256 tasks x 8-row segments ----
        // (col 0..31, seg 0..7). Lanes = consecutive cols -> conflict-free LDS,
        // coalesced STG. All 256 threads active.
        {
            const int col = tid & (HALF_W - 1);
            const int r0  = (tid >> 5) * CSEG;   // 0,8,...,56

            float v[KW + CSEG - 1];              // 24
            #pragma unroll
            for (int j = 0; j < KW + CSEG - 1; j++)
                v[j] = s_h[(r0 + j) * HS_PITCH + col];

            const int gx = x0 + c_base + col;
            float* p = dst + (size_t)(y0 + r0) * W + gx;

            float sum = 0.0f;
            #pragma unroll
            for (int j = 0; j < KW; j++) sum += v[j];
            *p = sum * scale;

            #pragma unroll
            for (int i = 1; i < CSEG; i++) {
                sum += v[i + KW - 1] - v[i - 1];
                p += W;
                *p = sum * scale;
            }
        }
        if (half == 0) __syncthreads();
    }
}

extern "C" void kernel_launch(void* const* d_in, const int* in_sizes, int n_in,
                              void* d_out, int out_size) {
    const float* x = (const float*)d_in[0];
    float* out = (float*)d_out;

    const int N = 8, C = 32, H = 512, W = 512;
    (void)in_sizes; (void)n_in; (void)out_size;

    dim3 grid(W / TILE_W, H / TILE_H, N * C);  // 8 x 8 x 256 = 16384 blocks
    box_filter_fused<<<grid, NTHREADS>>>(x, out, H, W);
}

// round 11
// speedup vs baseline: 1.1067x; 1.0138x over previous
#include <cuda_runtime.h>
#include <cuda_bf16.h>

// BoxFilter r=8 (k=17), separable, zero padding, fused (R6 structure, micro-opt).
// Phase A: cp.async.cg (zfill) 80x80 tile load; interior-x CTAs skip the
// per-vector x-predicate entirely (y-check only).
// Two 32-col halves: Phase B horizontal running sums (160 tasks) -> s_h,
// Phase C vertical running sums from registers (128 tasks x 16 rows) -> STG.cs.
// Smem 38.4 KB -> 5 CTAs/SM, regs capped at 40.
// Input x: [8, 32, 512, 512] f32 (256 images of 512x512), same-shape output.

#define RAD 8
#define KW  (2 * RAD + 1)          // 17
#define TILE_W 64
#define TILE_H 64
#define IN_W  (TILE_W + 2 * RAD)   // 80
#define IN_H  (TILE_H + 2 * RAD)   // 80
#define IN_PITCH 84                // 21x16B rows, odd -> LDS.128 conflict-free
#define HALF_W 32
#define HS_PITCH 36                // 9x16B rows, odd -> conflict-free
#define NTHREADS 256

__global__ __launch_bounds__(NTHREADS, 6)
void box_filter_fused(const float* __restrict__ in, float* __restrict__ out,
                      int H, int W) {
    __shared__ float s_in[IN_H * IN_PITCH];   // 80*84*4 = 26,880 B
    __shared__ float s_h [IN_H * HS_PITCH];   // 80*36*4 = 11,520 B (38.4 KB total)

    const int bx  = blockIdx.x;
    const int img = blockIdx.z;
    const int x0  = bx * TILE_W;
    const int y0  = blockIdx.y * TILE_H;
    const int tid = threadIdx.x;

    const float* __restrict__ src = in + (size_t)img * H * W;
    float* __restrict__ dst = out + (size_t)img * H * W;

    // ---- Phase A: cp.async tile load (80 rows x 20 float4), zero-filled OOB ----
    // Interior-x CTAs (bx 1..6): x always in range -> y-check only.
    {
        const bool interior_x = (bx > 0) && (bx < (W / TILE_W) - 1);
        int r = tid / 20;
        int q = tid - r * 20;
        if (interior_x) {
            #pragma unroll
            for (int it = 0; it < 7; it++) {
                const int idx = tid + it * NTHREADS;
                if (idx < IN_H * 20) {
                    const int gy = y0 - RAD + r;
                    const bool ok = (unsigned)gy < (unsigned)H;
                    const float* gptr = src + (ok ? ((size_t)gy * W + (x0 - RAD + 4 * q)) : 0);
                    unsigned saddr = (unsigned)__cvta_generic_to_shared(&s_in[r * IN_PITCH + 4 * q]);
                    const int sz = ok ? 16 : 0;  // src-size 0 -> zero fill
                    asm volatile("cp.async.cg.shared.global [%0], [%1], 16, %2;\n"
                                 :: "r"(saddr), "l"(gptr), "r"(sz));
                }
                r += 12; q += 16;
                if (q >= 20) { q -= 20; r += 1; }
            }
        } else {
            const int wlim = W - 4;
            #pragma unroll
            for (int it = 0; it < 7; it++) {
                const int idx = tid + it * NTHREADS;
                if (idx < IN_H * 20) {
                    const int gy = y0 - RAD + r;
                    const int gx = x0 - RAD + 4 * q;
                    const bool ok = ((unsigned)gy < (unsigned)H) &&
                                    ((unsigned)gx <= (unsigned)wlim);
                    const float* gptr = src + (ok ? ((size_t)gy * W + gx) : 0);
                    unsigned saddr = (unsigned)__cvta_generic_to_shared(&s_in[r * IN_PITCH + 4 * q]);
                    const int sz = ok ? 16 : 0;
                    asm volatile("cp.async.cg.shared.global [%0], [%1], 16, %2;\n"
                                 :: "r"(saddr), "l"(gptr), "r"(sz));
                }
                r += 12; q += 16;
                if (q >= 20) { q -= 20; r += 1; }
            }
        }
    }
    asm volatile("cp.async.commit_group;\n" ::: "memory");
    asm volatile("cp.async.wait_group 0;\n" ::: "memory");
    __syncthreads();

    const float scale = 1.0f / ((float)KW * (float)KW);

    #pragma unroll
    for (int half = 0; half < 2; half++) {
        const int c_base = half * HALF_W;   // tile-local output col base: 0 or 32

        // ---- Phase B: horizontal running sums (160 tasks) ----
        if (tid < IN_H * 2) {
            const int row = (tid < IN_H) ? tid : tid - IN_H;
            const int ci  = (tid < IN_H) ? c_base : c_base + 16;

            const float* p = &s_in[row * IN_PITCH + ci];
            float v[32];
            #pragma unroll
            for (int j = 0; j < 8; j++) {
                float4 q4 = *reinterpret_cast<const float4*>(p + 4 * j);
                v[4*j + 0] = q4.x; v[4*j + 1] = q4.y;
                v[4*j + 2] = q4.z; v[4*j + 3] = q4.w;
            }

            float h[16];
            float sum = 0.0f;
            #pragma unroll
            for (int j = 0; j < KW; j++) sum += v[j];
            h[0] = sum;
            #pragma unroll
            for (int c = 1; c < 16; c++) {
                sum += v[c + KW - 1] - v[c - 1];
                h[c] = sum;
            }

            float4* hp = reinterpret_cast<float4*>(&s_h[row * HS_PITCH + (ci - c_base)]);
            #pragma unroll
            for (int j = 0; j < 4; j++)
                hp[j] = make_float4(h[4*j], h[4*j+1], h[4*j+2], h[4*j+3]);
        }
        __syncthreads();

        // ---- Phase C: vertical running sums from registers + streaming store ----
        // 128 tasks: (local col 0..31, 16-row seg 0..3). Lanes = consecutive cols.
        if (tid < HALF_W * 4) {
            const int col = tid & (HALF_W - 1);
            const int r0  = (tid >> 5) << 4;     // 0,16,32,48

            float v[32];
            #pragma unroll
            for (int j = 0; j < 32; j++)
                v[j] = s_h[(r0 + j) * HS_PITCH + col];

            const int gx = x0 + c_base + col;
            float* p = dst + (size_t)(y0 + r0) * W + gx;

            float sum = 0.0f;
            #pragma unroll
            for (int j = 0; j < KW; j++) sum += v[j];
            __stcs(p, sum * scale);

            #pragma unroll
            for (int i = 1; i < 16; i++) {
                sum += v[i + KW - 1] - v[i - 1];
                p += W;
                __stcs(p, sum * scale);
            }
        }
        if (half == 0) __syncthreads();
    }
}

extern "C" void kernel_launch(void* const* d_in, const int* in_sizes, int n_in,
                              void* d_out, int out_size) {
    const float* x = (const float*)d_in[0];
    float* out = (float*)d_out;

    const int N = 8, C = 32, H = 512, W = 512;
    (void)in_sizes; (void)n_in; (void)out_size;

    dim3 grid(W / TILE_W, H / TILE_H, N * C);  // 8 x 8 x 256 = 16384 blocks
    box_filter_fused<<<grid, NTHREADS>>>(x, out, H, W);
}

// round 12
// speedup vs baseline: 1.1167x; 1.0090x over previous
#include <cuda_runtime.h>
#include <cuda_bf16.h>

// BoxFilter r=8 (k=17), separable, zero padding, fused.
// 288-thread CTA, 64x64 tile, two 32-col halves with PHASE MERGING:
//   fill -> sync -> B0 (160 thr) -> sync -> [B1 (thr 0..159) || C0 (thr 160..287)]
//   -> sync -> C1 (128 thr)
// B1 writes its h-sums into s_in's DEAD columns 0..31 (free after B0), so no
// second s_h buffer is needed: smem stays 38.4 KB -> 5 CTAs/SM = 45 warps.
// Input x: [8, 32, 512, 512] f32 (256 images of 512x512), same-shape output.

#define RAD 8
#define KW  (2 * RAD + 1)          // 17
#define TILE_W 64
#define TILE_H 64
#define IN_W  (TILE_W + 2 * RAD)   // 80
#define IN_H  (TILE_H + 2 * RAD)   // 80
#define IN_PITCH 84                // 21x16B rows -> near-conflict-free LDS/STS.128
#define HALF_W 32
#define HS_PITCH 36                // 9x16B rows
#define NTHREADS 288               // 9 warps

// Horizontal running sums for one half: 160 tasks (row 0..79, strip 0..1).
// Reads s_in cols [cin .. cin+47], writes 16 h-sums per task to (hbuf, hpitch).
__device__ __forceinline__ void phase_b(const float* s_in, float* hbuf,
                                        int hpitch, int cin, int t) {
    const int row = (t < IN_H) ? t : t - IN_H;
    const int stp = (t < IN_H) ? 0 : 16;

    const float* p = &s_in[row * IN_PITCH + cin + stp];
    float v[32];
    #pragma unroll
    for (int j = 0; j < 8; j++) {
        float4 q4 = *reinterpret_cast<const float4*>(p + 4 * j);
        v[4*j + 0] = q4.x; v[4*j + 1] = q4.y;
        v[4*j + 2] = q4.z; v[4*j + 3] = q4.w;
    }

    float h[16];
    float sum = 0.0f;
    #pragma unroll
    for (int j = 0; j < KW; j++) sum += v[j];
    h[0] = sum;
    #pragma unroll
    for (int c = 1; c < 16; c++) {
        sum += v[c + KW - 1] - v[c - 1];
        h[c] = sum;
    }

    float4* hp = reinterpret_cast<float4*>(&hbuf[row * hpitch + stp]);
    #pragma unroll
    for (int j = 0; j < 4; j++)
        hp[j] = make_float4(h[4*j], h[4*j+1], h[4*j+2], h[4*j+3]);
}

// Vertical running sums + streaming store for one half: 128 tasks
// (local col 0..31, 16-row seg 0..3) from (hbuf, hpitch).
__device__ __forceinline__ void phase_c(const float* hbuf, int hpitch,
                                        float* __restrict__ dst,
                                        int x0, int y0, int c_base,
                                        int t, int W) {
    const float scale = 1.0f / ((float)KW * (float)KW);
    const int col = t & (HALF_W - 1);
    const int r0  = (t >> 5) << 4;       // 0,16,32,48

    float v[32];
    #pragma unroll
    for (int j = 0; j < 32; j++)
        v[j] = hbuf[(r0 + j) * hpitch + col];

    float* p = dst + (size_t)(y0 + r0) * W + (x0 + c_base + col);

    float sum = 0.0f;
    #pragma unroll
    for (int j = 0; j < KW; j++) sum += v[j];
    __stcs(p, sum * scale);

    #pragma unroll
    for (int i = 1; i < 16; i++) {
        sum += v[i + KW - 1] - v[i - 1];
        p += W;
        __stcs(p, sum * scale);
    }
}

__global__ __launch_bounds__(NTHREADS, 5)
void box_filter_fused(const float* __restrict__ in, float* __restrict__ out,
                      int H, int W) {
    __shared__ float s_in[IN_H * IN_PITCH];   // 80*84*4 = 26,880 B
    __shared__ float s_h [IN_H * HS_PITCH];   // 80*36*4 = 11,520 B (38.4 KB total)

    const int bx  = blockIdx.x;
    const int img = blockIdx.z;
    const int x0  = bx * TILE_W;
    const int y0  = blockIdx.y * TILE_H;
    const int tid = threadIdx.x;

    const float* __restrict__ src = in + (size_t)img * H * W;
    float* __restrict__ dst = out + (size_t)img * H * W;

    // ---- Phase A: cp.async tile load (80 rows x 20 float4), zero-filled OOB ----
    // 1600 items over 288 threads (288 = 14*20 + 8 -> dr=14, dq=8 per iter).
    {
        const bool interior_x = (bx > 0) && (bx < (W / TILE_W) - 1);
        int r = tid / 20;
        int q = tid - r * 20;
        const int wlim = W - 4;
        #pragma unroll
        for (int it = 0; it < 6; it++) {
            const int idx = tid + it * NTHREADS;
            if (idx < IN_H * 20) {
                const int gy = y0 - RAD + r;
                const int gx = x0 - RAD + 4 * q;
                const bool ok = ((unsigned)gy < (unsigned)H) &&
                                (interior_x || (unsigned)gx <= (unsigned)wlim);
                const float* gptr = src + (ok ? ((size_t)gy * W + gx) : 0);
                unsigned saddr = (unsigned)__cvta_generic_to_shared(&s_in[r * IN_PITCH + 4 * q]);
                const int sz = ok ? 16 : 0;  // src-size 0 -> zero fill
                asm volatile("cp.async.cg.shared.global [%0], [%1], 16, %2;\n"
                             :: "r"(saddr), "l"(gptr), "r"(sz));
            }
            r += 14; q += 8;
            if (q >= 20) { q -= 20; r += 1; }
        }
    }
    asm volatile("cp.async.commit_group;\n" ::: "memory");
    asm volatile("cp.async.wait_group 0;\n" ::: "memory");
    __syncthreads();

    // ---- B0: h-sums for half 0 (reads s_in cols 0..47) -> s_h ----
    if (tid < IN_H * 2)
        phase_b(s_in, s_h, HS_PITCH, 0, tid);
    __syncthreads();

    // ---- Merged phase: B1 || C0 ----
    // B1 (threads 0..159): reads s_in cols 32..79, writes h-sums into the DEAD
    //   s_in cols 0..31 (only B0 ever read them).
    // C0 (threads 160..287): reads s_h, stores half-0 outputs.
    if (tid < IN_H * 2) {
        phase_b(s_in, s_in, IN_PITCH, HALF_W, tid);
    } else {
        phase_c(s_h, HS_PITCH, dst, x0, y0, 0, tid - IN_H * 2, W);
    }
    __syncthreads();

    // ---- C1: vertical pass for half 1 from s_in's embedded h-sums ----
    if (tid < HALF_W * 4)
        phase_c(s_in, IN_PITCH, dst, x0, y0, HALF_W, tid, W);
}

extern "C" void kernel_launch(void* const* d_in, const int* in_sizes, int n_in,
                              void* d_out, int out_size) {
    const float* x = (const float*)d_in[0];
    float* out = (float*)d_out;

    const int N = 8, C = 32, H = 512, W = 512;
    (void)in_sizes; (void)n_in; (void)out_size;

    dim3 grid(W / TILE_W, H / TILE_H, N * C);  // 8 x 8 x 256 = 16384 blocks
    box_filter_fused<<<grid, NTHREADS>>>(x, out, H, W);
}

// round 13
// speedup vs baseline: 1.1357x; 1.0170x over previous
#include <cuda_runtime.h>
#include <cuda_bf16.h>

// BoxFilter r=8 (k=17), separable, zero padding, fused.
// 256-thread CTA, 64x64 tile, two 32-col halves, phase-merged:
//   fill -> B0(160) -> [B1(160) || C0a(96)] -> [C0b(32) || C1(128)]
// s_h is pitch-32 with a 4-float row-rotation swizzle (conflict-free at
// minimal size); B1's h-sums go into s_in's dead cols 0..31 (same swizzle).
// Smem 37.1 KB -> 6 CTAs/SM (48 warps), regs cap 42.
// Input x: [8, 32, 512, 512] f32 (256 images of 512x512), same-shape output.

#define RAD 8
#define KW  (2 * RAD + 1)          // 17
#define TILE_W 64
#define TILE_H 64
#define IN_W  (TILE_W + 2 * RAD)   // 80
#define IN_H  (TILE_H + 2 * RAD)   // 80
#define IN_PITCH 84                // 21x16B rows -> conflict-free LDS.128
#define HALF_W 32
#define HS_PITCH 32                // swizzled (row-rotated) -> conflict-free
#define NTHREADS 256

// Horizontal running sums for one half-tile task (row, strip in {0,1}).
// Reads 32 inputs from s_in at column base cin+stp*16, writes 16 swizzled
// h-sums into (buf, pitch) at row `row`, half-local cols stp*16..stp*16+15.
__device__ __forceinline__ void phase_b(const float* s_in, float* buf,
                                        int pitch, int cin, int t) {
    const int row = (t < IN_H) ? t : t - IN_H;
    const int stp16 = (t < IN_H) ? 0 : 16;

    const float* p = &s_in[row * IN_PITCH + cin + stp16];
    float v[32];
    #pragma unroll
    for (int j = 0; j < 8; j++) {
        float4 q4 = *reinterpret_cast<const float4*>(p + 4 * j);
        v[4*j + 0] = q4.x; v[4*j + 1] = q4.y;
        v[4*j + 2] = q4.z; v[4*j + 3] = q4.w;
    }

    float h[16];
    float sum = 0.0f;
    #pragma unroll
    for (int j = 0; j < KW; j++) sum += v[j];
    h[0] = sum;
    #pragma unroll
    for (int c = 1; c < 16; c++) {
        sum += v[c + KW - 1] - v[c - 1];
        h[c] = sum;
    }

    // swizzled write: physical col = (logical col + 4*(row&7)) & 31
    const int rot = (row & 7) * 4;
    float* rp = &buf[row * pitch];
    #pragma unroll
    for (int k = 0; k < 4; k++) {
        const int off = (stp16 + 4 * k + rot) & 31;
        *reinterpret_cast<float4*>(rp + off) =
            make_float4(h[4*k], h[4*k+1], h[4*k+2], h[4*k+3]);
    }
}

// Vertical running sums + streaming store for one 16-row segment of one
// half-tile column. Reads swizzled h-sums from (buf, pitch).
__device__ __forceinline__ void phase_c(const float* buf, int pitch,
                                        float* __restrict__ dst,
                                        int x0, int y0, int c_base,
                                        int col, int r0, int W) {
    const float scale = 1.0f / ((float)KW * (float)KW);

    float v[32];
    #pragma unroll
    for (int j = 0; j < 32; j++) {
        const int pc = (col + ((j & 7) << 2)) & 31;  // r0 % 8 == 0
        v[j] = buf[(r0 + j) * pitch + pc];
    }

    float* p = dst + (size_t)(y0 + r0) * W + (x0 + c_base + col);

    float sum = 0.0f;
    #pragma unroll
    for (int j = 0; j < KW; j++) sum += v[j];
    __stcs(p, sum * scale);

    #pragma unroll
    for (int i = 1; i < 16; i++) {
        sum += v[i + KW - 1] - v[i - 1];
        p += W;
        __stcs(p, sum * scale);
    }
}

__global__ __launch_bounds__(NTHREADS, 6)
void box_filter_fused(const float* __restrict__ in, float* __restrict__ out,
                      int H, int W) {
    __shared__ float s_in[IN_H * IN_PITCH];   // 80*84*4 = 26,880 B
    __shared__ float s_h [IN_H * HS_PITCH];   // 80*32*4 = 10,240 B (37.1 KB total)

    const int bx  = blockIdx.x;
    const int img = blockIdx.z;
    const int x0  = bx * TILE_W;
    const int y0  = blockIdx.y * TILE_H;
    const int tid = threadIdx.x;

    const float* __restrict__ src = in + (size_t)img * H * W;
    float* __restrict__ dst = out + (size_t)img * H * W;

    // ---- Phase A: cp.async tile load (80 rows x 20 float4), zero-filled OOB ----
    {
        const bool interior_x = (bx > 0) && (bx < (W / TILE_W) - 1);
        const int wlim = W - 4;
        int r = tid / 20;
        int q = tid - r * 20;
        #pragma unroll
        for (int it = 0; it < 7; it++) {
            const int idx = tid + it * NTHREADS;
            if (idx < IN_H * 20) {
                const int gy = y0 - RAD + r;
                const int gx = x0 - RAD + 4 * q;
                const bool ok = ((unsigned)gy < (unsigned)H) &&
                                (interior_x || (unsigned)gx <= (unsigned)wlim);
                const float* gptr = src + (ok ? ((size_t)gy * W + gx) : 0);
                unsigned saddr = (unsigned)__cvta_generic_to_shared(&s_in[r * IN_PITCH + 4 * q]);
                const int sz = ok ? 16 : 0;  // src-size 0 -> zero fill
                asm volatile("cp.async.cg.shared.global [%0], [%1], 16, %2;\n"
                             :: "r"(saddr), "l"(gptr), "r"(sz));
            }
            r += 12; q += 16;
            if (q >= 20) { q -= 20; r += 1; }
        }
    }
    asm volatile("cp.async.commit_group;\n" ::: "memory");
    asm volatile("cp.async.wait_group 0;\n" ::: "memory");
    __syncthreads();

    // ---- B0: h-sums for half 0 (reads s_in cols 0..47) -> s_h (swizzled) ----
    if (tid < IN_H * 2)
        phase_b(s_in, s_h, HS_PITCH, 0, tid);
    __syncthreads();

    // ---- Merged: B1 (thr 0..159) || C0a (thr 160..255, segs 0..2) ----
    // B1 reads s_in cols 32..79, writes swizzled h-sums into DEAD s_in cols
    // 0..31. C0a reads s_h. All ranges disjoint.
    if (tid < IN_H * 2) {
        phase_b(s_in, s_in, IN_PITCH, HALF_W, tid);
    } else {
        const int t2 = tid - IN_H * 2;          // 0..95
        phase_c(s_h, HS_PITCH, dst, x0, y0, 0, t2 & 31, (t2 >> 5) << 4, W);
    }
    __syncthreads();

    // ---- Final: C0b (thr 0..31, seg 3) || C1 (thr 32..159, segs 0..3) ----
    if (tid < 32) {
        phase_c(s_h, HS_PITCH, dst, x0, y0, 0, tid, 48, W);
    } else if (tid < 160) {
        const int t3 = tid - 32;                // 0..127
        phase_c(s_in, IN_PITCH, dst, x0, y0, HALF_W, t3 & 31, (t3 >> 5) << 4, W);
    }
}

extern "C" void kernel_launch(void* const* d_in, const int* in_sizes, int n_in,
                              void* d_out, int out_size) {
    const float* x = (const float*)d_in[0];
    float* out = (float*)d_out;

    const int N = 8, C = 32, H = 512, W = 512;
    (void)in_sizes; (void)n_in; (void)out_size;

    dim3 grid(W / TILE_W, H / TILE_H, N * C);  // 8 x 8 x 256 = 16384 blocks
    box_filter_fused<<<grid, NTHREADS>>>(x, out, H, W);
}